// round 4
// baseline (speedup 1.0000x reference)
#include <cuda_runtime.h>
#include <cuda_bf16.h>
#include <cstdint>

// Problem shape (fixed)
#define N_IMG  16
#define C_IN   3
#define H_IN   224
#define W_IN   224
#define OC     128
#define OH     222
#define OW     222
#define PLANE  (H_IN * W_IN)            // 50176
#define NPIX   (N_IMG * PLANE)          // 802816
#define OPLANE (OH * OW)                // 49284
#define NPOS   (N_IMG * OPLANE)         // 788544 output positions
#define MTILES (NPOS / 16)              // 49284 (exact)
#define MT_PER_WARP 4
#define NWARPS (MTILES / MT_PER_WARP)   // 12321 (exact)

// ---------------- device scratch ------------------------------------------------
__device__ unsigned g_amax_x;
__device__ unsigned g_amax_w;
__device__ int      g_amax_v;
__device__ int   g_xq[NPIX];        // packed char4 (c0,c1,c2,0) per pixel
__device__ int4  g_im[NPOS * 2];    // dense im2col: 27 bytes + 5 zero pad (32B/pos)
__device__ int4  g_wqp[OC * 2];     // per oc: 32B = 27 wt bytes + zero + bias-int word

static __device__ __forceinline__ int pack4(int a, int b, int c, int d) {
    return (a & 0xFF) | ((b & 0xFF) << 8) | ((c & 0xFF) << 16) | ((d & 0xFF) << 24);
}

// int8 tensor-core tile: D(16x8,s32) = A(16x32,s8 row) * B(32x8,s8 col) + 0
static __device__ __forceinline__ void mma16n8k32(int& d0, int& d1, int& d2, int& d3,
                                                  int a0, int a1, int a2, int a3,
                                                  int b0, int b1) {
    asm volatile(
        "mma.sync.aligned.m16n8k32.row.col.s32.s8.s8.s32 "
        "{%0,%1,%2,%3},{%4,%5,%6,%7},{%8,%9},{%10,%11,%12,%13};"
        : "=r"(d0), "=r"(d1), "=r"(d2), "=r"(d3)
        : "r"(a0), "r"(a1), "r"(a2), "r"(a3), "r"(b0), "r"(b1),
          "r"(0), "r"(0), "r"(0), "r"(0));
}

// ---------------- K0: reset scalars ---------------------------------------------
__global__ void k_reset() {
    g_amax_x = 0u; g_amax_w = 0u; g_amax_v = 0;
}

// ---------------- K1: abs-max of x (float4 grid) and W --------------------------
__global__ void k_absmax(const float* __restrict__ x, const float* __restrict__ w) {
    int i = blockIdx.x * blockDim.x + threadIdx.x;
    float m = 0.0f;
    if (i < (N_IMG * C_IN * PLANE) / 4) {
        float4 v = reinterpret_cast<const float4*>(x)[i];
        m = fmaxf(fmaxf(fabsf(v.x), fabsf(v.y)), fmaxf(fabsf(v.z), fabsf(v.w)));
    }
    unsigned um = __reduce_max_sync(0xFFFFFFFFu, __float_as_uint(m));
    if ((threadIdx.x & 31) == 0 && um) atomicMax(&g_amax_x, um);

    if (blockIdx.x == 0) {
        float wm = 0.0f;
        for (int j = threadIdx.x; j < OC * C_IN * 9; j += blockDim.x)
            wm = fmaxf(wm, fabsf(w[j]));
        unsigned uw = __reduce_max_sync(0xFFFFFFFFu, __float_as_uint(wm));
        if ((threadIdx.x & 31) == 0) atomicMax(&g_amax_w, uw);
    }
}

// ---------------- K2: quantize x -> char4 words; W -> dense 32B records ---------
// byte order: index i = tap*3 + channel (i in [0,27)); bytes 27..31 pad/bias
#define XBLOCKS (NPIX / 256)   // 3136, exact
__global__ void k_quant(const float* __restrict__ x, const float* __restrict__ w,
                        const float* __restrict__ b) {
    const float s_in = fmaxf(__fdiv_rn(__uint_as_float(g_amax_x), 127.0f), 1e-8f);
    if (blockIdx.x < XBLOCKS) {
        int idx = blockIdx.x * 256 + threadIdx.x;
        int n  = idx / PLANE;
        int hw = idx - n * PLANE;
        const float* xp = x + (size_t)n * C_IN * PLANE + hw;
        int q[3];
#pragma unroll
        for (int c = 0; c < 3; c++) {
            float t = rintf(__fdiv_rn(xp[c * PLANE], s_in));
            t = fminf(fmaxf(t, -128.0f), 127.0f);
            q[c] = (int)t;
        }
        g_xq[idx] = pack4(q[0], q[1], q[2], 0);
    } else if (threadIdx.x < OC) {
        const float s_w = fmaxf(__fdiv_rn(__uint_as_float(g_amax_w), 7.0f), 1e-8f);
        int oc = threadIdx.x;
        int m[28];
#pragma unroll
        for (int i = 0; i < 27; i++) {
            int t = i / 3, c = i - t * 3;              // tap-major, channel-minor
            float v = rintf(__fdiv_rn(w[oc * 27 + c * 9 + t], s_w));
            v = fminf(fmaxf(v, -7.0f), 7.0f);
            m[i] = (int)v;
        }
        m[27] = 0;
        int wd[8];
#pragma unroll
        for (int j = 0; j < 7; j++)
            wd[j] = pack4(m[4 * j], m[4 * j + 1], m[4 * j + 2], m[4 * j + 3]);
        float s_b = s_in * s_w;
        float bt = rintf(__fdiv_rn(b[oc], s_b));
        bt = fminf(fmaxf(bt, -2.0e9f), 2.0e9f);
        wd[7] = (int)bt;   // bias word: multiplies ZERO A-bytes in the mma (inert)
        g_wqp[oc * 2]     = make_int4(wd[0], wd[1], wd[2], wd[3]);
        g_wqp[oc * 2 + 1] = make_int4(wd[4], wd[5], wd[6], wd[7]);
    }
}

// ---------------- K3: im2col repack (9 sparse words -> 32B dense record) --------
__global__ void k_im2col() {
    int p = blockIdx.x * 256 + threadIdx.x;
    if (p >= NPOS) return;
    int n  = p / OPLANE;
    int r  = p - n * OPLANE;
    int oh = r / OW;
    int ow = r - oh * OW;
    const int* xp = g_xq + (n * H_IN + oh) * W_IN + ow;
    int t0 = xp[0],            t1 = xp[1],            t2 = xp[2];
    int t3 = xp[W_IN],         t4 = xp[W_IN + 1],     t5 = xp[W_IN + 2];
    int t6 = xp[2 * W_IN],     t7 = xp[2 * W_IN + 1], t8 = xp[2 * W_IN + 2];
    int4 lo, hi;
    lo.x = __byte_perm(t0, t1, 0x4210);
    lo.y = __byte_perm(t1, t2, 0x5421);
    lo.z = __byte_perm(t2, t3, 0x6542);
    lo.w = __byte_perm(t4, t5, 0x4210);
    hi.x = __byte_perm(t5, t6, 0x5421);
    hi.y = __byte_perm(t6, t7, 0x6542);
    hi.z = __byte_perm(t8, 0,  0x4210);
    hi.w = 0;
    g_im[p * 2]     = lo;
    g_im[p * 2 + 1] = hi;
}

// ---------------- K4/K5: tensor-core conv. STORE=0: max pass --------------------
template <int STORE>
__global__ void __launch_bounds__(256) k_conv(float* __restrict__ out) {
    __shared__ int swq[OC * 8];                        // full weight records (1KB)
    if (threadIdx.x < OC * 8 / 4) {
        reinterpret_cast<int4*>(swq)[threadIdx.x] =
            reinterpret_cast<const int4*>(g_wqp)[threadIdx.x];
    }
    __syncthreads();

    int lane = threadIdx.x & 31;
    int gw   = blockIdx.x * 8 + (threadIdx.x >> 5);    // global warp id
    if (gw >= NWARPS) return;
    int g   = lane >> 2;                               // groupID (row/col in frag)
    int tig = lane & 3;

    // B fragments for all 16 n-tiles (col-major: oc-record bytes are the K dim)
    int b0[16], b1[16], biA[16], biB[16];
#pragma unroll
    for (int j = 0; j < 16; j++) {
        b0[j]  = swq[(8 * j + g) * 8 + tig];
        b1[j]  = swq[(8 * j + g) * 8 + 4 + tig];
        biA[j] = swq[(8 * j + 2 * tig) * 8 + 7];       // bias for C col 8j+2*tig
        biB[j] = swq[(8 * j + 2 * tig + 1) * 8 + 7];   // bias for C col 8j+2*tig+1
    }

    float kf = 0.f, s_out = 0.f;
    if (STORE) {
        const float s_in = fmaxf(__fdiv_rn(__uint_as_float(g_amax_x), 127.0f), 1e-8f);
        const float s_w  = fmaxf(__fdiv_rn(__uint_as_float(g_amax_w), 7.0f), 1e-8f);
        float s_b  = s_in * s_w;
        float maxy = s_b * (float)g_amax_v;
        s_out = fmaxf(__fdiv_rn(maxy, 127.0f), 1e-8f);
        kf = __fdiv_rn(s_b, s_out);
    }

    const int* imw = reinterpret_cast<const int*>(g_im);
    int mx = -2147483647, mn = 2147483647;

#pragma unroll
    for (int mt = 0; mt < MT_PER_WARP; mt++) {
        int p0 = (gw * MT_PER_WARP + mt) * 16;
        int pA = p0 + g, pB = pA + 8;                  // this thread's two A rows
        int a0 = imw[pA * 8 + tig];
        int a1 = imw[pB * 8 + tig];
        int a2 = imw[pA * 8 + 4 + tig];
        int a3 = imw[pB * 8 + 4 + tig];

        float *fA = nullptr, *fB = nullptr;
        if (STORE) {
            int nA = pA / OPLANE, rA = pA - nA * OPLANE;
            int nB = pB / OPLANE, rB = pB - nB * OPLANE;
            fA = out + (size_t)nA * OC * OPLANE + rA;
            fB = out + (size_t)nB * OC * OPLANE + rB;
        }

#pragma unroll
        for (int j = 0; j < 16; j++) {
            int c0, c1, c2, c3;
            mma16n8k32(c0, c1, c2, c3, a0, a1, a2, a3, b0[j], b1[j]);
            int s0 = c0 + biA[j], s1 = c1 + biB[j];
            int s2 = c2 + biA[j], s3 = c3 + biB[j];
            if (STORE) {
                // clamp provably inactive: |s*kf| <= 127 by construction of s_out
                size_t colA = (size_t)(8 * j + 2 * tig) * OPLANE;
                fA[colA]          = rintf((float)s0 * kf) * s_out;
                fA[colA + OPLANE] = rintf((float)s1 * kf) * s_out;
                fB[colA]          = rintf((float)s2 * kf) * s_out;
                fB[colA + OPLANE] = rintf((float)s3 * kf) * s_out;
            } else {
                mx = max(mx, max(max(s0, s1), max(s2, s3)));
                mn = min(mn, min(min(s0, s1), min(s2, s3)));
            }
        }
    }
    if (!STORE) {
        int am = max(mx, -mn);
        am = __reduce_max_sync(0xFFFFFFFFu, am);
        if (lane == 0) atomicMax(&g_amax_v, am);
    }
}

// ---------------- launcher --------------------------------------------------------
extern "C" void kernel_launch(void* const* d_in, const int* in_sizes, int n_in,
                              void* d_out, int out_size) {
    const float *x = nullptr, *w = nullptr, *b = nullptr;
    for (int i = 0; i < n_in; i++) {
        if (in_sizes[i] == N_IMG * C_IN * PLANE)      x = (const float*)d_in[i];
        else if (in_sizes[i] == OC * C_IN * 9)        w = (const float*)d_in[i];
        else if (in_sizes[i] == OC)                   b = (const float*)d_in[i];
    }
    float* out = (float*)d_out;

    k_reset<<<1, 32>>>();

    int n4 = (N_IMG * C_IN * PLANE) / 4;
    k_absmax<<<(n4 + 255) / 256, 256>>>(x, w);

    k_quant<<<XBLOCKS + 1, 256>>>(x, w, b);

    k_im2col<<<(NPOS + 255) / 256, 256>>>();

    int cblocks = (NWARPS + 7) / 8;       // 1541
    k_conv<0><<<cblocks, 256>>>(out);
    k_conv<1><<<cblocks, 256>>>(out);
}

// round 5
// speedup vs baseline: 1.0237x; 1.0237x over previous
#include <cuda_runtime.h>
#include <cuda_bf16.h>
#include <cstdint>

// Problem shape (fixed)
#define N_IMG  16
#define C_IN   3
#define H_IN   224
#define W_IN   224
#define OC     128
#define OH     222
#define OW     222
#define PLANE  (H_IN * W_IN)            // 50176
#define NPIX   (N_IMG * PLANE)          // 802816
#define OPLANE (OH * OW)                // 49284 (even)
#define NPOS   (N_IMG * OPLANE)         // 788544 output positions
#define NPAIRS (NPOS / 2)               // 394272
#define PCHUNK 64                       // positions per block (NPOS/64 = 12321 exact)
#define NBLK   (NPOS / PCHUNK)          // 12321

// ---------------- device scratch ------------------------------------------------
__device__ unsigned g_amax_x;
__device__ unsigned g_amax_w;
__device__ int      g_amax_v;
__device__ int   g_xq[NPIX];        // packed char4 (c0,c1,c2,0) per pixel
__device__ int4  g_im[NPOS * 2];    // dense im2col: 27 bytes + 5 zero pad (32B/pos)
__device__ int4  g_wqp[OC * 2];     // per oc: 27 wt bytes + zero pad + bias word 7
__device__ int   g_ob[NPAIRS];      // per position-pair: n*OC*OPLANE + oh*OW + ow

static __device__ __forceinline__ int pack4(int a, int b, int c, int d) {
    return (a & 0xFF) | ((b & 0xFF) << 8) | ((c & 0xFF) << 16) | ((d & 0xFF) << 24);
}

// D(16x8,s32) = A(16x32,s8 row-major) * B(32x8,s8 col-major)
static __device__ __forceinline__ void mma16n8k32(int& d0, int& d1, int& d2, int& d3,
                                                  int a0, int a1, int a2, int a3,
                                                  int b0, int b1) {
    asm volatile(
        "mma.sync.aligned.m16n8k32.row.col.s32.s8.s8.s32 "
        "{%0,%1,%2,%3},{%4,%5,%6,%7},{%8,%9},{%10,%11,%12,%13};"
        : "=r"(d0), "=r"(d1), "=r"(d2), "=r"(d3)
        : "r"(a0), "r"(a1), "r"(a2), "r"(a3), "r"(b0), "r"(b1),
          "r"(0), "r"(0), "r"(0), "r"(0));
}

// ---------------- K0: reset scalars ---------------------------------------------
__global__ void k_reset() {
    g_amax_x = 0u; g_amax_w = 0u; g_amax_v = 0;
}

// ---------------- K1: abs-max of x (float4 grid) and W --------------------------
__global__ void k_absmax(const float* __restrict__ x, const float* __restrict__ w) {
    int i = blockIdx.x * blockDim.x + threadIdx.x;
    float m = 0.0f;
    if (i < (N_IMG * C_IN * PLANE) / 4) {
        float4 v = reinterpret_cast<const float4*>(x)[i];
        m = fmaxf(fmaxf(fabsf(v.x), fabsf(v.y)), fmaxf(fabsf(v.z), fabsf(v.w)));
    }
    unsigned um = __reduce_max_sync(0xFFFFFFFFu, __float_as_uint(m));
    if ((threadIdx.x & 31) == 0 && um) atomicMax(&g_amax_x, um);

    if (blockIdx.x == 0) {
        float wm = 0.0f;
        for (int j = threadIdx.x; j < OC * C_IN * 9; j += blockDim.x)
            wm = fmaxf(wm, fabsf(w[j]));
        unsigned uw = __reduce_max_sync(0xFFFFFFFFu, __float_as_uint(wm));
        if ((threadIdx.x & 31) == 0) atomicMax(&g_amax_w, uw);
    }
}

// ---------------- K2: quantize x -> char4 words; W -> dense 32B records ---------
// record byte order: i = tap*3 + channel (i in [0,27)); bytes 27..30 zero; 28..31 bias
#define XBLOCKS (NPIX / 256)   // 3136, exact
__global__ void k_quant(const float* __restrict__ x, const float* __restrict__ w,
                        const float* __restrict__ b) {
    const float s_in = fmaxf(__fdiv_rn(__uint_as_float(g_amax_x), 127.0f), 1e-8f);
    if (blockIdx.x < XBLOCKS) {
        int idx = blockIdx.x * 256 + threadIdx.x;
        int n  = idx / PLANE;
        int hw = idx - n * PLANE;
        const float* xp = x + (size_t)n * C_IN * PLANE + hw;
        int q[3];
#pragma unroll
        for (int c = 0; c < 3; c++) {
            float t = rintf(__fdiv_rn(xp[c * PLANE], s_in));
            t = fminf(fmaxf(t, -128.0f), 127.0f);
            q[c] = (int)t;
        }
        g_xq[idx] = pack4(q[0], q[1], q[2], 0);
    } else if (threadIdx.x < OC) {
        const float s_w = fmaxf(__fdiv_rn(__uint_as_float(g_amax_w), 7.0f), 1e-8f);
        int oc = threadIdx.x;
        int m[28];
#pragma unroll
        for (int i = 0; i < 27; i++) {
            int t = i / 3, c = i - t * 3;              // tap-major, channel-minor
            float v = rintf(__fdiv_rn(w[oc * 27 + c * 9 + t], s_w));
            v = fminf(fmaxf(v, -7.0f), 7.0f);
            m[i] = (int)v;
        }
        m[27] = 0;
        int wd[8];
#pragma unroll
        for (int j = 0; j < 7; j++)
            wd[j] = pack4(m[4 * j], m[4 * j + 1], m[4 * j + 2], m[4 * j + 3]);
        float s_b = s_in * s_w;
        float bt = rintf(__fdiv_rn(b[oc], s_b));
        bt = fminf(fmaxf(bt, -2.0e9f), 2.0e9f);
        wd[7] = (int)bt;   // bias word: multiplies ZERO B-bytes in the mma (inert)
        g_wqp[oc * 2]     = make_int4(wd[0], wd[1], wd[2], wd[3]);
        g_wqp[oc * 2 + 1] = make_int4(wd[4], wd[5], wd[6], wd[7]);
    }
}

// ---------------- K3: im2col repack, 2 positions per thread + offset table ------
static __device__ __forceinline__ void pack_rec(int t0, int t1, int t2,
                                                int t3, int t4, int t5,
                                                int t6, int t7, int t8,
                                                int4& lo, int4& hi) {
    lo.x = __byte_perm(t0, t1, 0x4210);
    lo.y = __byte_perm(t1, t2, 0x5421);
    lo.z = __byte_perm(t2, t3, 0x6542);
    lo.w = __byte_perm(t4, t5, 0x4210);
    hi.x = __byte_perm(t5, t6, 0x5421);
    hi.y = __byte_perm(t6, t7, 0x6542);
    hi.z = __byte_perm(t8, 0,  0x4210);
    hi.w = 0;
}

__global__ void k_im2col() {
    int pr = blockIdx.x * 256 + threadIdx.x;     // pair index
    if (pr >= NPAIRS) return;
    int n  = pr / (OPLANE / 2);
    int r2 = (pr - n * (OPLANE / 2)) * 2;
    int oh = r2 / OW;
    int ow = r2 - oh * OW;                       // even, <= 220
    const int* xp = g_xq + (n * H_IN + oh) * W_IN + ow;
    int w00 = xp[0],            w01 = xp[1],            w02 = xp[2],            w03 = xp[3];
    int w10 = xp[W_IN],         w11 = xp[W_IN + 1],     w12 = xp[W_IN + 2],     w13 = xp[W_IN + 3];
    int w20 = xp[2 * W_IN],     w21 = xp[2 * W_IN + 1], w22 = xp[2 * W_IN + 2], w23 = xp[2 * W_IN + 3];
    int4 lo, hi;
    pack_rec(w00, w01, w02, w10, w11, w12, w20, w21, w22, lo, hi);
    g_im[pr * 4]     = lo;
    g_im[pr * 4 + 1] = hi;
    pack_rec(w01, w02, w03, w11, w12, w13, w21, w22, w23, lo, hi);
    g_im[pr * 4 + 2] = lo;
    g_im[pr * 4 + 3] = hi;
    g_ob[pr] = n * OC * OPLANE + oh * OW + ow;
}

// ---------------- K4/K5: tensor-core conv, weights=M ocs, positions=N -----------
template <int STORE>
__global__ void __launch_bounds__(256) k_conv(float* __restrict__ out) {
    int lane = threadIdx.x & 31;
    int g    = lane >> 2;        // groupID: C rows (oc g, g+8), B col g
    int tig  = lane & 3;
    int ocb  = (threadIdx.x >> 5) * 16;                // warp -> 16-oc tile

    const int* wq = reinterpret_cast<const int*>(g_wqp);
    int a0  = __ldg(wq + (ocb + g) * 8 + tig);
    int a1  = __ldg(wq + (ocb + g + 8) * 8 + tig);
    int a2  = __ldg(wq + (ocb + g) * 8 + 4 + tig);
    int a3  = __ldg(wq + (ocb + g + 8) * 8 + 4 + tig);
    int bg  = __ldg(wq + (ocb + g) * 8 + 7);           // bias for C row g
    int bg8 = __ldg(wq + (ocb + g + 8) * 8 + 7);       // bias for C row g+8

    float kf = 0.f, s_out = 0.f;
    if (STORE) {
        const float s_in = fmaxf(__fdiv_rn(__uint_as_float(g_amax_x), 127.0f), 1e-8f);
        const float s_w  = fmaxf(__fdiv_rn(__uint_as_float(g_amax_w), 7.0f), 1e-8f);
        float s_b  = s_in * s_w;
        float maxy = s_b * (float)g_amax_v;
        s_out = fmaxf(__fdiv_rn(maxy, 127.0f), 1e-8f);
        kf = __fdiv_rn(s_b, s_out);
    }

    const int* im = reinterpret_cast<const int*>(g_im);
    int pb = blockIdx.x * PCHUNK;
    int mx0 = -2147483647, mn0 = 2147483647;
    int mx1 = -2147483647, mn1 = 2147483647;

#pragma unroll
    for (int nt = 0; nt < PCHUNK / 8; nt++) {          // 8 N-tiles of 8 positions
        int pN = pb + nt * 8;
        int b0 = __ldg(im + (pN + g) * 8 + tig);       // col g, k bytes 4*tig..
        int b1 = __ldg(im + (pN + g) * 8 + 4 + tig);   // col g, k bytes 16+4*tig..
        int c0, c1, c2, c3;
        mma16n8k32(c0, c1, c2, c3, a0, a1, a2, a3, b0, b1);
        if (STORE) {
            int ofs = __ldg(g_ob + (pN >> 1) + tig);   // base for positions 2tig,2tig+1
            float2 q0, q1;
            // clamp provably inactive: |(c+bi)*kf| <= 127 by construction of s_out
            q0.x = rintf((float)(c0 + bg)  * kf) * s_out;
            q0.y = rintf((float)(c1 + bg)  * kf) * s_out;
            q1.x = rintf((float)(c2 + bg8) * kf) * s_out;
            q1.y = rintf((float)(c3 + bg8) * kf) * s_out;
            *reinterpret_cast<float2*>(out + ofs + (ocb + g) * OPLANE)     = q0;
            *reinterpret_cast<float2*>(out + ofs + (ocb + g + 8) * OPLANE) = q1;
        } else {
            mx0 = max(mx0, max(c0, c1)); mn0 = min(mn0, min(c0, c1));
            mx1 = max(mx1, max(c2, c3)); mn1 = min(mn1, min(c2, c3));
        }
    }
    if (!STORE) {
        int am = max(max(mx0 + bg, -(mn0 + bg)), max(mx1 + bg8, -(mn1 + bg8)));
        am = __reduce_max_sync(0xFFFFFFFFu, am);
        if (lane == 0) atomicMax(&g_amax_v, am);
    }
}

// ---------------- launcher --------------------------------------------------------
extern "C" void kernel_launch(void* const* d_in, const int* in_sizes, int n_in,
                              void* d_out, int out_size) {
    const float *x = nullptr, *w = nullptr, *b = nullptr;
    for (int i = 0; i < n_in; i++) {
        if (in_sizes[i] == N_IMG * C_IN * PLANE)      x = (const float*)d_in[i];
        else if (in_sizes[i] == OC * C_IN * 9)        w = (const float*)d_in[i];
        else if (in_sizes[i] == OC)                   b = (const float*)d_in[i];
    }
    float* out = (float*)d_out;

    k_reset<<<1, 32>>>();

    int n4 = (N_IMG * C_IN * PLANE) / 4;
    k_absmax<<<(n4 + 255) / 256, 256>>>(x, w);

    k_quant<<<XBLOCKS + 1, 256>>>(x, w, b);

    k_im2col<<<(NPAIRS + 255) / 256, 256>>>();

    k_conv<0><<<NBLK, 256>>>(out);
    k_conv<1><<<NBLK, 256>>>(out);
}

// round 6
// speedup vs baseline: 1.6293x; 1.5916x over previous
#include <cuda_runtime.h>
#include <cuda_bf16.h>
#include <cstdint>

// Problem shape (fixed)
#define N_IMG  16
#define C_IN   3
#define H_IN   224
#define W_IN   224
#define OC     128
#define OH     222
#define OW     222
#define PLANE  (H_IN * W_IN)            // 50176
#define NPIX   (N_IMG * PLANE)          // 802816
#define OPLANE (OH * OW)                // 49284 (even)
#define NPOS   (N_IMG * OPLANE)         // 788544
#define NPAIRS (NPOS / 2)               // 394272 conv threads (2 positions each)

// ---------------- device scratch ------------------------------------------------
__device__ unsigned g_amax_x;
__device__ unsigned g_amax_w;
__device__ int      g_amax_v;
__device__ int   g_xq[NPIX];        // packed char4 (c0,c1,c2,0) per pixel
__device__ int4  g_im[NPOS * 2];    // dense im2col: 27 bytes + 5 zero pad (32B/pos)
__device__ int4  g_wqp[OC * 2];     // per oc: 27 wt bytes + pad; word 7 = bias int
__device__ int   g_ob[NPAIRS];      // per pair: n*OC*OPLANE + oh*OW + ow

static __device__ __forceinline__ int pack4(int a, int b, int c, int d) {
    return (a & 0xFF) | ((b & 0xFF) << 8) | ((c & 0xFF) << 16) | ((d & 0xFF) << 24);
}

// ---------------- K0: reset scalars ---------------------------------------------
__global__ void k_reset() {
    g_amax_x = 0u; g_amax_w = 0u; g_amax_v = 0;
}

// ---------------- K1: abs-max of x (float4 grid) and W --------------------------
__global__ void k_absmax(const float* __restrict__ x, const float* __restrict__ w) {
    int i = blockIdx.x * blockDim.x + threadIdx.x;
    float m = 0.0f;
    if (i < (N_IMG * C_IN * PLANE) / 4) {
        float4 v = reinterpret_cast<const float4*>(x)[i];
        m = fmaxf(fmaxf(fabsf(v.x), fabsf(v.y)), fmaxf(fabsf(v.z), fabsf(v.w)));
    }
    unsigned um = __reduce_max_sync(0xFFFFFFFFu, __float_as_uint(m));
    if ((threadIdx.x & 31) == 0 && um) atomicMax(&g_amax_x, um);

    if (blockIdx.x == 0) {
        float wm = 0.0f;
        for (int j = threadIdx.x; j < OC * C_IN * 9; j += blockDim.x)
            wm = fmaxf(wm, fabsf(w[j]));
        unsigned uw = __reduce_max_sync(0xFFFFFFFFu, __float_as_uint(wm));
        if ((threadIdx.x & 31) == 0) atomicMax(&g_amax_w, uw);
    }
}

// ---------------- K2: quantize x (4 pixels/thread) ; W -> dense 32B records -----
// record byte order: i = tap*3 + channel (i in [0,27)); word 7 = bias int
#define QBLOCKS (NPIX / 1024)   // 784, exact (4 pixels per thread)
__global__ void k_quant(const float* __restrict__ x, const float* __restrict__ w,
                        const float* __restrict__ b) {
    const float s_in = fmaxf(__fdiv_rn(__uint_as_float(g_amax_x), 127.0f), 1e-8f);
    if (blockIdx.x < QBLOCKS) {
        int idx = (blockIdx.x * 256 + threadIdx.x) * 4;   // pixel index, 4 at a time
        int n  = idx / PLANE;                              // same n for all 4 (PLANE%4==0)
        int hw = idx - n * PLANE;
        const float* xp = x + (size_t)n * C_IN * PLANE + hw;
        float4 c0 = *reinterpret_cast<const float4*>(xp);
        float4 c1 = *reinterpret_cast<const float4*>(xp + PLANE);
        float4 c2 = *reinterpret_cast<const float4*>(xp + 2 * PLANE);
        const float ri = __fdiv_rn(1.0f, s_in);
        int4 o;
        {
            int q0 = (int)fminf(fmaxf(rintf(c0.x * ri), -128.f), 127.f);
            int q1 = (int)fminf(fmaxf(rintf(c1.x * ri), -128.f), 127.f);
            int q2 = (int)fminf(fmaxf(rintf(c2.x * ri), -128.f), 127.f);
            o.x = pack4(q0, q1, q2, 0);
        }
        {
            int q0 = (int)fminf(fmaxf(rintf(c0.y * ri), -128.f), 127.f);
            int q1 = (int)fminf(fmaxf(rintf(c1.y * ri), -128.f), 127.f);
            int q2 = (int)fminf(fmaxf(rintf(c2.y * ri), -128.f), 127.f);
            o.y = pack4(q0, q1, q2, 0);
        }
        {
            int q0 = (int)fminf(fmaxf(rintf(c0.z * ri), -128.f), 127.f);
            int q1 = (int)fminf(fmaxf(rintf(c1.z * ri), -128.f), 127.f);
            int q2 = (int)fminf(fmaxf(rintf(c2.z * ri), -128.f), 127.f);
            o.z = pack4(q0, q1, q2, 0);
        }
        {
            int q0 = (int)fminf(fmaxf(rintf(c0.w * ri), -128.f), 127.f);
            int q1 = (int)fminf(fmaxf(rintf(c1.w * ri), -128.f), 127.f);
            int q2 = (int)fminf(fmaxf(rintf(c2.w * ri), -128.f), 127.f);
            o.w = pack4(q0, q1, q2, 0);
        }
        *reinterpret_cast<int4*>(g_xq + idx) = o;
    } else if (threadIdx.x < OC) {
        const float s_w = fmaxf(__fdiv_rn(__uint_as_float(g_amax_w), 7.0f), 1e-8f);
        int oc = threadIdx.x;
        int m[28];
#pragma unroll
        for (int i = 0; i < 27; i++) {
            int t = i / 3, c = i - t * 3;              // tap-major, channel-minor
            float v = rintf(__fdiv_rn(w[oc * 27 + c * 9 + t], s_w));
            v = fminf(fmaxf(v, -7.0f), 7.0f);
            m[i] = (int)v;
        }
        m[27] = 0;
        int wd[8];
#pragma unroll
        for (int j = 0; j < 7; j++)
            wd[j] = pack4(m[4 * j], m[4 * j + 1], m[4 * j + 2], m[4 * j + 3]);
        float s_b = s_in * s_w;
        float bt = rintf(__fdiv_rn(b[oc], s_b));
        bt = fminf(fmaxf(bt, -2.0e9f), 2.0e9f);
        wd[7] = (int)bt;                               // bias int (never multiplied)
        g_wqp[oc * 2]     = make_int4(wd[0], wd[1], wd[2], wd[3]);
        g_wqp[oc * 2 + 1] = make_int4(wd[4], wd[5], wd[6], wd[7]);
    }
}

// ---------------- K3: im2col repack, 2 positions/thread + offset table ----------
static __device__ __forceinline__ void pack_rec(int t0, int t1, int t2,
                                                int t3, int t4, int t5,
                                                int t6, int t7, int t8,
                                                int4& lo, int4& hi) {
    lo.x = __byte_perm(t0, t1, 0x4210);
    lo.y = __byte_perm(t1, t2, 0x5421);
    lo.z = __byte_perm(t2, t3, 0x6542);
    lo.w = __byte_perm(t4, t5, 0x4210);
    hi.x = __byte_perm(t5, t6, 0x5421);
    hi.y = __byte_perm(t6, t7, 0x6542);
    hi.z = __byte_perm(t8, 0,  0x4210);
    hi.w = 0;
}

__global__ void k_im2col() {
    int pr = blockIdx.x * 256 + threadIdx.x;     // pair index
    if (pr >= NPAIRS) return;
    int n  = pr / (OPLANE / 2);
    int r2 = (pr - n * (OPLANE / 2)) * 2;
    int oh = r2 / OW;
    int ow = r2 - oh * OW;                       // even, <= 220
    const int* xp = g_xq + (n * H_IN + oh) * W_IN + ow;
    int w00 = xp[0],        w01 = xp[1],            w02 = xp[2],            w03 = xp[3];
    int w10 = xp[W_IN],     w11 = xp[W_IN + 1],     w12 = xp[W_IN + 2],     w13 = xp[W_IN + 3];
    int w20 = xp[2 * W_IN], w21 = xp[2 * W_IN + 1], w22 = xp[2 * W_IN + 2], w23 = xp[2 * W_IN + 3];
    int4 lo, hi;
    pack_rec(w00, w01, w02, w10, w11, w12, w20, w21, w22, lo, hi);
    g_im[pr * 4]     = lo;
    g_im[pr * 4 + 1] = hi;
    pack_rec(w01, w02, w03, w11, w12, w13, w21, w22, w23, lo, hi);
    g_im[pr * 4 + 2] = lo;
    g_im[pr * 4 + 3] = hi;
    g_ob[pr] = n * OC * OPLANE + oh * OW + ow;
}

// 7-word dp4a dot, accumulator initialized with init
static __device__ __forceinline__ int dot7(const int4& xa, const int4& xb,
                                           const int4& wa, const int4& wb, int init) {
    int s = __dp4a(xa.x, wa.x, init);
    s = __dp4a(xa.y, wa.y, s); s = __dp4a(xa.z, wa.z, s); s = __dp4a(xa.w, wa.w, s);
    s = __dp4a(xb.x, wb.x, s); s = __dp4a(xb.y, wb.y, s); s = __dp4a(xb.z, wb.z, s);
    return s;
}

// ---------------- K4/K5: conv over dense im2col, 2 pos/thread. STORE=0: max -----
template <int STORE>
__global__ void __launch_bounds__(256) k_conv(float* __restrict__ out) {
    __shared__ int4 sw[OC * 2];                        // 4KB weight records
    sw[threadIdx.x] = g_wqp[threadIdx.x];              // 256 threads = 256 int4
    __syncthreads();

    int pr = blockIdx.x * 256 + threadIdx.x;
    if (pr >= NPAIRS) return;

    const int4* ip = g_im + (size_t)pr * 4;            // 64B consecutive per thread
    int4 x0a = ip[0], x0b = ip[1];
    int4 x1a = ip[2], x1b = ip[3];

    float kf = 0.f, s_out = 0.f;
    float* obase = nullptr;
    if (STORE) {
        const float s_in = fmaxf(__fdiv_rn(__uint_as_float(g_amax_x), 127.0f), 1e-8f);
        const float s_w  = fmaxf(__fdiv_rn(__uint_as_float(g_amax_w), 7.0f), 1e-8f);
        float s_b  = s_in * s_w;
        float maxy = s_b * (float)g_amax_v;
        s_out = fmaxf(__fdiv_rn(maxy, 127.0f), 1e-8f);
        kf = __fdiv_rn(s_b, s_out);
        obase = out + __ldg(g_ob + pr);
    }

    int mx = -2147483647, mn = 2147483647;
#pragma unroll 4
    for (int oc = 0; oc < OC; oc++) {
        int4 wa = sw[oc * 2], wb = sw[oc * 2 + 1];
        int bi = wb.w;
        int a0 = dot7(x0a, x0b, wa, wb, bi);
        int a1 = dot7(x1a, x1b, wa, wb, bi);
        if (STORE) {
            // clamp provably inactive: |a*kf| <= 127 by construction of s_out
            float2 q;
            q.x = rintf((float)a0 * kf) * s_out;
            q.y = rintf((float)a1 * kf) * s_out;
            *reinterpret_cast<float2*>(obase + (size_t)oc * OPLANE) = q;
        } else {
            mx = max(mx, max(a0, a1));
            mn = min(mn, min(a0, a1));
        }
    }
    if (!STORE) {
        int am = max(mx, -mn);
        am = __reduce_max_sync(0xFFFFFFFFu, am);
        if ((threadIdx.x & 31) == 0) atomicMax(&g_amax_v, am);
    }
}

// ---------------- launcher --------------------------------------------------------
extern "C" void kernel_launch(void* const* d_in, const int* in_sizes, int n_in,
                              void* d_out, int out_size) {
    const float *x = nullptr, *w = nullptr, *b = nullptr;
    for (int i = 0; i < n_in; i++) {
        if (in_sizes[i] == N_IMG * C_IN * PLANE)      x = (const float*)d_in[i];
        else if (in_sizes[i] == OC * C_IN * 9)        w = (const float*)d_in[i];
        else if (in_sizes[i] == OC)                   b = (const float*)d_in[i];
    }
    float* out = (float*)d_out;

    k_reset<<<1, 32>>>();

    int n4 = (N_IMG * C_IN * PLANE) / 4;
    k_absmax<<<(n4 + 255) / 256, 256>>>(x, w);

    k_quant<<<QBLOCKS + 1, 256>>>(x, w, b);

    k_im2col<<<(NPAIRS + 255) / 256, 256>>>();

    int cblocks = (NPAIRS + 255) / 256;   // 1541
    k_conv<0><<<cblocks, 256>>>(out);
    k_conv<1><<<cblocks, 256>>>(out);
}

// round 7
// speedup vs baseline: 1.7261x; 1.0594x over previous
#include <cuda_runtime.h>
#include <cuda_bf16.h>
#include <cstdint>

// Problem shape (fixed)
#define N_IMG  16
#define C_IN   3
#define H_IN   224
#define W_IN   224
#define OC     128
#define OH     222
#define OW     222
#define PLANE  (H_IN * W_IN)            // 50176
#define NPIX   (N_IMG * PLANE)          // 802816
#define OPLANE (OH * OW)                // 49284 (even)
#define NPOS   (N_IMG * OPLANE)         // 788544
#define NPAIRS (NPOS / 2)               // 394272 conv threads (2 positions each)

// ---------------- device scratch ------------------------------------------------
// g_scal[0] = amax_x bits, g_scal[1] = amax_w bits, g_scal[2] = amax_v (int)
__device__ unsigned g_scal[3];
__device__ int   g_xq[NPIX];        // packed char4 (c0,c1,c2,0) per pixel
__device__ int4  g_im[NPOS * 2];    // dense im2col: 27 bytes + 5 zero pad (32B/pos)
__device__ int4  g_wqp[OC * 2];     // per oc: 27 wt bytes + pad; word 7 = bias int
__device__ int   g_ob[NPAIRS];      // per pair: n*OC*OPLANE + oh*OW + ow

static __device__ __forceinline__ int pack4(int a, int b, int c, int d) {
    return (a & 0xFF) | ((b & 0xFF) << 8) | ((c & 0xFF) << 16) | ((d & 0xFF) << 24);
}

// ---------------- K1: abs-max of x (float4 grid) and W --------------------------
__global__ void k_absmax(const float* __restrict__ x, const float* __restrict__ w) {
    int i = blockIdx.x * blockDim.x + threadIdx.x;
    float m = 0.0f;
    if (i < (N_IMG * C_IN * PLANE) / 4) {
        float4 v = reinterpret_cast<const float4*>(x)[i];
        m = fmaxf(fmaxf(fabsf(v.x), fabsf(v.y)), fmaxf(fabsf(v.z), fabsf(v.w)));
    }
    unsigned um = __reduce_max_sync(0xFFFFFFFFu, __float_as_uint(m));
    if ((threadIdx.x & 31) == 0 && um) atomicMax(&g_scal[0], um);

    if (blockIdx.x == 0) {
        float wm = 0.0f;
        for (int j = threadIdx.x; j < OC * C_IN * 9; j += blockDim.x)
            wm = fmaxf(wm, fabsf(w[j]));
        unsigned uw = __reduce_max_sync(0xFFFFFFFFu, __float_as_uint(wm));
        if ((threadIdx.x & 31) == 0) atomicMax(&g_scal[1], uw);
    }
}

// ---------------- K2: quantize x (4 pixels/thread) ; W -> dense 32B records -----
// record byte order: i = tap*3 + channel (i in [0,27)); word 7 = bias int
#define QBLOCKS (NPIX / 1024)   // 784, exact (4 pixels per thread)
__global__ void k_quant(const float* __restrict__ x, const float* __restrict__ w,
                        const float* __restrict__ b) {
    const float s_in = fmaxf(__fdiv_rn(__uint_as_float(g_scal[0]), 127.0f), 1e-8f);
    if (blockIdx.x < QBLOCKS) {
        int idx = (blockIdx.x * 256 + threadIdx.x) * 4;   // pixel index, 4 at a time
        int n  = idx / PLANE;                              // same n for all 4 (PLANE%4==0)
        int hw = idx - n * PLANE;
        const float* xp = x + (size_t)n * C_IN * PLANE + hw;
        float4 c0 = *reinterpret_cast<const float4*>(xp);
        float4 c1 = *reinterpret_cast<const float4*>(xp + PLANE);
        float4 c2 = *reinterpret_cast<const float4*>(xp + 2 * PLANE);
        const float ri = __fdiv_rn(1.0f, s_in);
        int4 o;
        {
            int q0 = (int)fminf(fmaxf(rintf(c0.x * ri), -128.f), 127.f);
            int q1 = (int)fminf(fmaxf(rintf(c1.x * ri), -128.f), 127.f);
            int q2 = (int)fminf(fmaxf(rintf(c2.x * ri), -128.f), 127.f);
            o.x = pack4(q0, q1, q2, 0);
        }
        {
            int q0 = (int)fminf(fmaxf(rintf(c0.y * ri), -128.f), 127.f);
            int q1 = (int)fminf(fmaxf(rintf(c1.y * ri), -128.f), 127.f);
            int q2 = (int)fminf(fmaxf(rintf(c2.y * ri), -128.f), 127.f);
            o.y = pack4(q0, q1, q2, 0);
        }
        {
            int q0 = (int)fminf(fmaxf(rintf(c0.z * ri), -128.f), 127.f);
            int q1 = (int)fminf(fmaxf(rintf(c1.z * ri), -128.f), 127.f);
            int q2 = (int)fminf(fmaxf(rintf(c2.z * ri), -128.f), 127.f);
            o.z = pack4(q0, q1, q2, 0);
        }
        {
            int q0 = (int)fminf(fmaxf(rintf(c0.w * ri), -128.f), 127.f);
            int q1 = (int)fminf(fmaxf(rintf(c1.w * ri), -128.f), 127.f);
            int q2 = (int)fminf(fmaxf(rintf(c2.w * ri), -128.f), 127.f);
            o.w = pack4(q0, q1, q2, 0);
        }
        *reinterpret_cast<int4*>(g_xq + idx) = o;
    } else if (threadIdx.x < OC) {
        const float s_w = fmaxf(__fdiv_rn(__uint_as_float(g_scal[1]), 7.0f), 1e-8f);
        int oc = threadIdx.x;
        int m[28];
#pragma unroll
        for (int i = 0; i < 27; i++) {
            int t = i / 3, c = i - t * 3;              // tap-major, channel-minor
            float v = rintf(__fdiv_rn(w[oc * 27 + c * 9 + t], s_w));
            v = fminf(fmaxf(v, -7.0f), 7.0f);
            m[i] = (int)v;
        }
        m[27] = 0;
        int wd[8];
#pragma unroll
        for (int j = 0; j < 7; j++)
            wd[j] = pack4(m[4 * j], m[4 * j + 1], m[4 * j + 2], m[4 * j + 3]);
        float s_b = s_in * s_w;
        float bt = rintf(__fdiv_rn(b[oc], s_b));
        bt = fminf(fmaxf(bt, -2.0e9f), 2.0e9f);
        wd[7] = (int)bt;                               // bias int (never multiplied)
        g_wqp[oc * 2]     = make_int4(wd[0], wd[1], wd[2], wd[3]);
        g_wqp[oc * 2 + 1] = make_int4(wd[4], wd[5], wd[6], wd[7]);
    }
}

// pack one 32B im2col record from 9 pixel words
static __device__ __forceinline__ void pack_rec(int t0, int t1, int t2,
                                                int t3, int t4, int t5,
                                                int t6, int t7, int t8,
                                                int4& lo, int4& hi) {
    lo.x = __byte_perm(t0, t1, 0x4210);
    lo.y = __byte_perm(t1, t2, 0x5421);
    lo.z = __byte_perm(t2, t3, 0x6542);
    lo.w = __byte_perm(t4, t5, 0x4210);
    hi.x = __byte_perm(t5, t6, 0x5421);
    hi.y = __byte_perm(t6, t7, 0x6542);
    hi.z = __byte_perm(t8, 0,  0x4210);
    hi.w = 0;
}

// 7-word dp4a dot, accumulator initialized with init
static __device__ __forceinline__ int dot7(const int4& xa, const int4& xb,
                                           const int4& wa, const int4& wb, int init) {
    int s = __dp4a(xa.x, wa.x, init);
    s = __dp4a(xa.y, wa.y, s); s = __dp4a(xa.z, wa.z, s); s = __dp4a(xa.w, wa.w, s);
    s = __dp4a(xb.x, wb.x, s); s = __dp4a(xb.y, wb.y, s); s = __dp4a(xb.z, wb.z, s);
    return s;
}

// ---------------- K3: FUSED im2col + max pass -----------------------------------
// builds the dense records (hidden under the dp4a shadow) and reduces max|acc+bi|
__global__ void __launch_bounds__(256) k_convmax() {
    __shared__ int4 sw[OC * 2];                        // 4KB weight records
    sw[threadIdx.x] = g_wqp[threadIdx.x];
    __syncthreads();

    int pr = blockIdx.x * 256 + threadIdx.x;           // pair index
    if (pr >= NPAIRS) return;
    int n  = pr / (OPLANE / 2);
    int r2 = (pr - n * (OPLANE / 2)) * 2;
    int oh = r2 / OW;
    int ow = r2 - oh * OW;                             // even, <= 220
    const int* xp = g_xq + (n * H_IN + oh) * W_IN + ow;
    int w00 = xp[0],        w01 = xp[1],            w02 = xp[2],            w03 = xp[3];
    int w10 = xp[W_IN],     w11 = xp[W_IN + 1],     w12 = xp[W_IN + 2],     w13 = xp[W_IN + 3];
    int w20 = xp[2 * W_IN], w21 = xp[2 * W_IN + 1], w22 = xp[2 * W_IN + 2], w23 = xp[2 * W_IN + 3];

    int4 x0a, x0b, x1a, x1b;
    pack_rec(w00, w01, w02, w10, w11, w12, w20, w21, w22, x0a, x0b);
    pack_rec(w01, w02, w03, w11, w12, w13, w21, w22, w23, x1a, x1b);
    int4* op = g_im + (size_t)pr * 4;
    op[0] = x0a; op[1] = x0b; op[2] = x1a; op[3] = x1b;
    g_ob[pr] = n * OC * OPLANE + oh * OW + ow;

    int mx = -2147483647, mn = 2147483647;
#pragma unroll 4
    for (int oc = 0; oc < OC; oc++) {
        int4 wa = sw[oc * 2], wb = sw[oc * 2 + 1];
        int bi = wb.w;
        int a0 = dot7(x0a, x0b, wa, wb, bi);
        int a1 = dot7(x1a, x1b, wa, wb, bi);
        mx = max(mx, max(a0, a1));
        mn = min(mn, min(a0, a1));
    }
    int am = max(mx, -mn);
    am = (int)__reduce_max_sync(0xFFFFFFFFu, (unsigned)max(am, 0));
    if ((threadIdx.x & 31) == 0) atomicMax((int*)&g_scal[2], am);
}

// ---------------- K4: store pass over dense im2col ------------------------------
__global__ void __launch_bounds__(256) k_convstore(float* __restrict__ out) {
    __shared__ int4 sw[OC * 2];
    sw[threadIdx.x] = g_wqp[threadIdx.x];
    __syncthreads();

    int pr = blockIdx.x * 256 + threadIdx.x;
    if (pr >= NPAIRS) return;

    const int4* ip = g_im + (size_t)pr * 4;            // 64B consecutive per thread
    int4 x0a = ip[0], x0b = ip[1];
    int4 x1a = ip[2], x1b = ip[3];

    const float s_in = fmaxf(__fdiv_rn(__uint_as_float(g_scal[0]), 127.0f), 1e-8f);
    const float s_w  = fmaxf(__fdiv_rn(__uint_as_float(g_scal[1]), 7.0f), 1e-8f);
    float s_b  = s_in * s_w;
    float maxy = s_b * (float)(int)g_scal[2];
    float s_out = fmaxf(__fdiv_rn(maxy, 127.0f), 1e-8f);
    float kf = __fdiv_rn(s_b, s_out);
    float* obase = out + __ldg(g_ob + pr);

#pragma unroll 4
    for (int oc = 0; oc < OC; oc++) {
        int4 wa = sw[oc * 2], wb = sw[oc * 2 + 1];
        int bi = wb.w;
        int a0 = dot7(x0a, x0b, wa, wb, bi);
        int a1 = dot7(x1a, x1b, wa, wb, bi);
        // clamp provably inactive: |a*kf| <= 127 by construction of s_out
        float2 q;
        q.x = rintf((float)a0 * kf) * s_out;
        q.y = rintf((float)a1 * kf) * s_out;
        *reinterpret_cast<float2*>(obase + (size_t)oc * OPLANE) = q;
    }
}

// ---------------- launcher --------------------------------------------------------
extern "C" void kernel_launch(void* const* d_in, const int* in_sizes, int n_in,
                              void* d_out, int out_size) {
    const float *x = nullptr, *w = nullptr, *b = nullptr;
    for (int i = 0; i < n_in; i++) {
        if (in_sizes[i] == N_IMG * C_IN * PLANE)      x = (const float*)d_in[i];
        else if (in_sizes[i] == OC * C_IN * 9)        w = (const float*)d_in[i];
        else if (in_sizes[i] == OC)                   b = (const float*)d_in[i];
    }
    float* out = (float*)d_out;

    // reset scalars via memset node (cheaper than a kernel launch)
    void* scal_addr = nullptr;
    cudaGetSymbolAddress(&scal_addr, g_scal);
    cudaMemsetAsync(scal_addr, 0, 3 * sizeof(unsigned), 0);

    int n4 = (N_IMG * C_IN * PLANE) / 4;
    k_absmax<<<(n4 + 255) / 256, 256>>>(x, w);

    k_quant<<<QBLOCKS + 1, 256>>>(x, w, b);

    int cblocks = (NPAIRS + 255) / 256;   // 1541
    k_convmax<<<cblocks, 256>>>();
    k_convstore<<<cblocks, 256>>>(out);
}

// round 8
// speedup vs baseline: 1.8360x; 1.0636x over previous
#include <cuda_runtime.h>
#include <cuda_bf16.h>
#include <cstdint>

// Problem shape (fixed)
#define N_IMG  16
#define C_IN   3
#define H_IN   224
#define W_IN   224
#define OC     128
#define OH     222
#define OW     222
#define PLANE  (H_IN * W_IN)            // 50176
#define NPIX   (N_IMG * PLANE)          // 802816
#define OPLANE (OH * OW)                // 49284 (even)
#define NPOS   (N_IMG * OPLANE)         // 788544
#define NPAIRS (NPOS / 2)               // 394272 conv threads (2 positions each)

// ---------------- device scratch ------------------------------------------------
// g_scal[0] = amax_x bits, g_scal[1] = amax_w bits, g_scal[2] = amax_v (int)
__device__ unsigned g_scal[3];
__device__ int   g_xq[NPIX];        // packed char4 (c0,c1,c2,0) per pixel
__device__ int4  g_im[NPOS * 2];    // dense im2col: 27 bytes + 5 zero pad (32B/pos)
__device__ int4  g_wqp[OC * 2];     // per oc: 27 wt bytes + pad; word 7 = bias int
__device__ int   g_ob[NPAIRS];      // per pair: n*OC*OPLANE + oh*OW + ow

static __device__ __forceinline__ int pack4(int a, int b, int c, int d) {
    return (a & 0xFF) | ((b & 0xFF) << 8) | ((c & 0xFF) << 16) | ((d & 0xFF) << 24);
}

// ---------------- K1: abs-max of x (float4 grid) and W --------------------------
__global__ void k_absmax(const float* __restrict__ x, const float* __restrict__ w) {
    int i = blockIdx.x * blockDim.x + threadIdx.x;
    float m = 0.0f;
    if (i < (N_IMG * C_IN * PLANE) / 4) {
        float4 v = reinterpret_cast<const float4*>(x)[i];
        m = fmaxf(fmaxf(fabsf(v.x), fabsf(v.y)), fmaxf(fabsf(v.z), fabsf(v.w)));
    }
    unsigned um = __reduce_max_sync(0xFFFFFFFFu, __float_as_uint(m));
    if ((threadIdx.x & 31) == 0 && um) atomicMax(&g_scal[0], um);

    if (blockIdx.x == 0) {
        float wm = 0.0f;
        for (int j = threadIdx.x; j < OC * C_IN * 9; j += blockDim.x)
            wm = fmaxf(wm, fabsf(w[j]));
        unsigned uw = __reduce_max_sync(0xFFFFFFFFu, __float_as_uint(wm));
        if ((threadIdx.x & 31) == 0) atomicMax(&g_scal[1], uw);
    }
}

// ---------------- K2: quantize x (4 pixels/thread) ; W -> dense 32B records -----
// record byte order: i = tap*3 + channel (i in [0,27)); word 7 = bias int
#define QBLOCKS (NPIX / 1024)   // 784, exact
__global__ void k_quant(const float* __restrict__ x, const float* __restrict__ w,
                        const float* __restrict__ b) {
    const float s_in = fmaxf(__fdiv_rn(__uint_as_float(g_scal[0]), 127.0f), 1e-8f);
    if (blockIdx.x < QBLOCKS) {
        int idx = (blockIdx.x * 256 + threadIdx.x) * 4;
        int n  = idx / PLANE;
        int hw = idx - n * PLANE;
        const float* xp = x + (size_t)n * C_IN * PLANE + hw;
        float4 c0 = *reinterpret_cast<const float4*>(xp);
        float4 c1 = *reinterpret_cast<const float4*>(xp + PLANE);
        float4 c2 = *reinterpret_cast<const float4*>(xp + 2 * PLANE);
        const float ri = __fdiv_rn(1.0f, s_in);
        int4 o;
        {
            int q0 = (int)fminf(fmaxf(rintf(c0.x * ri), -128.f), 127.f);
            int q1 = (int)fminf(fmaxf(rintf(c1.x * ri), -128.f), 127.f);
            int q2 = (int)fminf(fmaxf(rintf(c2.x * ri), -128.f), 127.f);
            o.x = pack4(q0, q1, q2, 0);
        }
        {
            int q0 = (int)fminf(fmaxf(rintf(c0.y * ri), -128.f), 127.f);
            int q1 = (int)fminf(fmaxf(rintf(c1.y * ri), -128.f), 127.f);
            int q2 = (int)fminf(fmaxf(rintf(c2.y * ri), -128.f), 127.f);
            o.y = pack4(q0, q1, q2, 0);
        }
        {
            int q0 = (int)fminf(fmaxf(rintf(c0.z * ri), -128.f), 127.f);
            int q1 = (int)fminf(fmaxf(rintf(c1.z * ri), -128.f), 127.f);
            int q2 = (int)fminf(fmaxf(rintf(c2.z * ri), -128.f), 127.f);
            o.z = pack4(q0, q1, q2, 0);
        }
        {
            int q0 = (int)fminf(fmaxf(rintf(c0.w * ri), -128.f), 127.f);
            int q1 = (int)fminf(fmaxf(rintf(c1.w * ri), -128.f), 127.f);
            int q2 = (int)fminf(fmaxf(rintf(c2.w * ri), -128.f), 127.f);
            o.w = pack4(q0, q1, q2, 0);
        }
        *reinterpret_cast<int4*>(g_xq + idx) = o;
    } else if (threadIdx.x < OC) {
        const float s_w = fmaxf(__fdiv_rn(__uint_as_float(g_scal[1]), 7.0f), 1e-8f);
        int oc = threadIdx.x;
        int m[28];
#pragma unroll
        for (int i = 0; i < 27; i++) {
            int t = i / 3, c = i - t * 3;              // tap-major, channel-minor
            float v = rintf(__fdiv_rn(w[oc * 27 + c * 9 + t], s_w));
            v = fminf(fmaxf(v, -7.0f), 7.0f);
            m[i] = (int)v;
        }
        m[27] = 0;
        int wd[8];
#pragma unroll
        for (int j = 0; j < 7; j++)
            wd[j] = pack4(m[4 * j], m[4 * j + 1], m[4 * j + 2], m[4 * j + 3]);
        float s_b = s_in * s_w;
        float bt = rintf(__fdiv_rn(b[oc], s_b));
        bt = fminf(fmaxf(bt, -2.0e9f), 2.0e9f);
        wd[7] = (int)bt;                               // bias int (never multiplied)
        g_wqp[oc * 2]     = make_int4(wd[0], wd[1], wd[2], wd[3]);
        g_wqp[oc * 2 + 1] = make_int4(wd[4], wd[5], wd[6], wd[7]);
    }
}

// pack one 32B im2col record from 9 pixel words
static __device__ __forceinline__ void pack_rec(int t0, int t1, int t2,
                                                int t3, int t4, int t5,
                                                int t6, int t7, int t8,
                                                int4& lo, int4& hi) {
    lo.x = __byte_perm(t0, t1, 0x4210);
    lo.y = __byte_perm(t1, t2, 0x5421);
    lo.z = __byte_perm(t2, t3, 0x6542);
    lo.w = __byte_perm(t4, t5, 0x4210);
    hi.x = __byte_perm(t5, t6, 0x5421);
    hi.y = __byte_perm(t6, t7, 0x6542);
    hi.z = __byte_perm(t8, 0,  0x4210);
    hi.w = 0;
}

// 7-word dp4a dot as TWO independent chains (4 + 3), merged by one IADD (alu pipe)
static __device__ __forceinline__ int dot7(const int4& xa, const int4& xb,
                                           const int4& wa, const int4& wb, int init) {
    int s = __dp4a(xa.x, wa.x, init);
    s = __dp4a(xa.y, wa.y, s);
    s = __dp4a(xa.z, wa.z, s);
    s = __dp4a(xa.w, wa.w, s);
    int t = __dp4a(xb.x, wb.x, 0);
    t = __dp4a(xb.y, wb.y, t);
    t = __dp4a(xb.z, wb.z, t);
    return s + t;
}

// ---------------- K3: FUSED im2col + max pass -----------------------------------
__global__ void __launch_bounds__(256) k_convmax() {
    __shared__ int4 sw[OC * 2];                        // 4KB weight records
    sw[threadIdx.x] = g_wqp[threadIdx.x];
    __syncthreads();

    int pr = blockIdx.x * 256 + threadIdx.x;           // pair index
    if (pr >= NPAIRS) return;
    int n  = pr / (OPLANE / 2);
    int r2 = (pr - n * (OPLANE / 2)) * 2;
    int oh = r2 / OW;
    int ow = r2 - oh * OW;                             // even, <= 220
    const int* xp = g_xq + (n * H_IN + oh) * W_IN + ow;
    int w00 = xp[0],        w01 = xp[1],            w02 = xp[2],            w03 = xp[3];
    int w10 = xp[W_IN],     w11 = xp[W_IN + 1],     w12 = xp[W_IN + 2],     w13 = xp[W_IN + 3];
    int w20 = xp[2 * W_IN], w21 = xp[2 * W_IN + 1], w22 = xp[2 * W_IN + 2], w23 = xp[2 * W_IN + 3];

    int4 x0a, x0b, x1a, x1b;
    pack_rec(w00, w01, w02, w10, w11, w12, w20, w21, w22, x0a, x0b);
    pack_rec(w01, w02, w03, w11, w12, w13, w21, w22, w23, x1a, x1b);
    int4* op = g_im + (size_t)pr * 4;
    op[0] = x0a; op[1] = x0b; op[2] = x1a; op[3] = x1b;
    g_ob[pr] = n * OC * OPLANE + oh * OW + ow;

    int mx = -2147483647, mn = 2147483647;
#pragma unroll 4
    for (int oc = 0; oc < OC; oc++) {
        int4 wa = sw[oc * 2], wb = sw[oc * 2 + 1];
        int bi = wb.w;
        int a0 = dot7(x0a, x0b, wa, wb, bi);
        int a1 = dot7(x1a, x1b, wa, wb, bi);
        mx = max(mx, max(a0, a1));
        mn = min(mn, min(a0, a1));
    }
    int am = max(mx, -mn);
    am = (int)__reduce_max_sync(0xFFFFFFFFu, (unsigned)max(am, 0));
    if ((threadIdx.x & 31) == 0) atomicMax((int*)&g_scal[2], am);
}

// ---------------- K4: store pass, f32x2 epilogue + streaming stores --------------
__global__ void __launch_bounds__(256) k_convstore(float* __restrict__ out) {
    __shared__ int4 sw[OC * 2];
    sw[threadIdx.x] = g_wqp[threadIdx.x];
    __syncthreads();

    int pr = blockIdx.x * 256 + threadIdx.x;
    if (pr >= NPAIRS) return;

    const int4* ip = g_im + (size_t)pr * 4;            // 64B consecutive per thread
    int4 x0a = ip[0], x0b = ip[1];
    int4 x1a = ip[2], x1b = ip[3];

    const float s_in = fmaxf(__fdiv_rn(__uint_as_float(g_scal[0]), 127.0f), 1e-8f);
    const float s_w  = fmaxf(__fdiv_rn(__uint_as_float(g_scal[1]), 7.0f), 1e-8f);
    float s_b   = s_in * s_w;
    float maxy  = s_b * (float)(int)g_scal[2];
    float s_out = fmaxf(__fdiv_rn(maxy, 127.0f), 1e-8f);
    float kf    = __fdiv_rn(s_b, s_out);
    const float MAGIC = 12582912.0f;                   // 1.5 * 2^23

    // packed f32x2 constants
    unsigned long long k2, m2, nm2, s2;
    asm("mov.b64 %0, {%1,%1};" : "=l"(k2)  : "f"(kf));
    asm("mov.b64 %0, {%1,%1};" : "=l"(m2)  : "f"(MAGIC));
    asm("mov.b64 %0, {%1,%1};" : "=l"(nm2) : "f"(-MAGIC));
    asm("mov.b64 %0, {%1,%1};" : "=l"(s2)  : "f"(s_out));

    float* obase = out + __ldg(g_ob + pr);

#pragma unroll 4
    for (int oc = 0; oc < OC; oc++) {
        int4 wa = sw[oc * 2], wb = sw[oc * 2 + 1];
        int bi = wb.w;
        int a0 = dot7(x0a, x0b, wa, wb, bi);
        int a1 = dot7(x1a, x1b, wa, wb, bi);
        // magic rounding, both lanes at once: q = rint(a*kf) * s_out
        float f0 = (float)a0, f1 = (float)a1;
        unsigned long long p, q;
        asm("mov.b64 %0, {%1,%2};" : "=l"(p) : "f"(f0), "f"(f1));
        asm("fma.rn.f32x2 %0, %1, %2, %3;" : "=l"(q) : "l"(p), "l"(k2), "l"(m2));
        asm("add.rn.f32x2 %0, %1, %2;" : "=l"(q) : "l"(q), "l"(nm2));
        asm("mul.rn.f32x2 %0, %1, %2;" : "=l"(q) : "l"(q), "l"(s2));
        // streaming 8B store (write-once output, evict-first)
        asm volatile("st.global.cs.b64 [%0], %1;"
                     :: "l"(obase + (size_t)oc * OPLANE), "l"(q) : "memory");
    }
}

// ---------------- launcher --------------------------------------------------------
extern "C" void kernel_launch(void* const* d_in, const int* in_sizes, int n_in,
                              void* d_out, int out_size) {
    const float *x = nullptr, *w = nullptr, *b = nullptr;
    for (int i = 0; i < n_in; i++) {
        if (in_sizes[i] == N_IMG * C_IN * PLANE)      x = (const float*)d_in[i];
        else if (in_sizes[i] == OC * C_IN * 9)        w = (const float*)d_in[i];
        else if (in_sizes[i] == OC)                   b = (const float*)d_in[i];
    }
    float* out = (float*)d_out;

    void* scal_addr = nullptr;
    cudaGetSymbolAddress(&scal_addr, g_scal);
    cudaMemsetAsync(scal_addr, 0, 3 * sizeof(unsigned), 0);

    int n4 = (N_IMG * C_IN * PLANE) / 4;
    k_absmax<<<(n4 + 255) / 256, 256>>>(x, w);

    k_quant<<<QBLOCKS + 1, 256>>>(x, w, b);

    int cblocks = (NPAIRS + 255) / 256;   // 1541
    k_convmax<<<cblocks, 256>>>();
    k_convstore<<<cblocks, 256>>>(out);
}